// round 12
// baseline (speedup 1.0000x reference)
#include <cuda_runtime.h>

// Depthwise 1D conv: B=8, F=64, L=131072, K=9, pad=4 (SAME).
// x:      (B, F, L) float32, row (b,f) at (b*F + f)*L
// kernel: (F, 1, 9) float32
// out:    (F, B, 1, L) float32, row (f,b) at (f*B + b)*L
//
// QPT=8 as two load4/compute4 waves: wave 2's loads are issued before wave 1's
// compute, so >=4 loads stay in flight, but only ~5 float4 live at once
// -> <=42 regs (launch_bounds 256,6) -> occ ~70% AND deep MLP.
// All LDG/STG lane-adjacent (fully coalesced). Halo via lane-wrap indexed
// shuffles; cross-chunk/cross-wave halo is register-resident. Only 2 true
// edge loads per warp. __ldcs/__stcs: streams touched once -> evict-first.

#define Lc 131072
#define Fc 64
#define Bc 8
#define QUADS_PER_ROW (Lc / 4)            // 32768 = 2^15
#define QPT 8                             // quads per thread (2 waves of 4)
#define G 4                               // quads per wave

__global__ __launch_bounds__(256, 6) void dwconv1d_kernel(
    const float* __restrict__ x,
    const float* __restrict__ w,
    float* __restrict__ out)
{
    const unsigned FULL = 0xFFFFFFFFu;
    int lane = threadIdx.x & 31;
    int warp = threadIdx.x >> 5;

    // Block covers 2048 contiguous quads, all within one row (32768 % 2048 == 0)
    int qblock = blockIdx.x * (256 * QPT);
    int row = qblock >> 15;               // b*F + f
    int f = row & (Fc - 1);
    int b = row >> 6;

    const float* xr = x + (size_t)row * Lc;
    float* orow = out + ((size_t)(f * Bc + b)) * Lc;

    // 9 warp-uniform weight loads (whole block shares f)
    const float* wf = w + f * 9;
    float k0 = wf[0], k1 = wf[1], k2 = wf[2], k3 = wf[3], k4 = wf[4],
          k5 = wf[5], k6 = wf[6], k7 = wf[7], k8 = wf[8];

    // Warp's within-row quad base (warp spans quads [qw, qw+256))
    int qw = (qblock & (QUADS_PER_ROW - 1)) + warp * (32 * QPT);

    // True edge quads (only the wrap lane's value is read through shuffles)
    float4 eprev = make_float4(0.f, 0.f, 0.f, 0.f);  // quad qw-1   (lane 31)
    float4 enext = make_float4(0.f, 0.f, 0.f, 0.f);  // quad qw+256 (lane 0)
    if (lane == 31 && qw != 0)
        eprev = __ldcs(reinterpret_cast<const float4*>(xr + (qw << 2) - 4));
    if (lane == 0 && qw + 32 * QPT != QUADS_PER_ROW)
        enext = __ldcs(reinterpret_cast<const float4*>(xr + ((qw + 32 * QPT) << 2)));

    int up = (lane + 31) & 31;   // lane-1 mod 32
    int dn = (lane + 1) & 31;    // lane+1 mod 32

    float4 c[G], c2[G];

    // Wave-1 loads
#pragma unroll
    for (int j = 0; j < G; j++)
        c[j] = __ldcs(reinterpret_cast<const float4*>(xr + ((qw + j * 32 + lane) << 2)));
    // Wave-2 loads issued before wave-1 compute (keeps MLP deep)
#pragma unroll
    for (int j = 0; j < G; j++)
        c2[j] = __ldcs(reinterpret_cast<const float4*>(xr + ((qw + (G + j) * 32 + lane) << 2)));

    // carry: lane31 needs c[G-1] as prev for wave2 j=0; lane0 needs c2[0] as
    // next for wave1 j=G-1. Both register-resident.

#pragma unroll
    for (int wv = 0; wv < 2; wv++) {
#pragma unroll
        for (int j = 0; j < G; j++) {
            float4 cur  = (wv == 0) ? c[j]  : c2[j];

            float4 sm = cur;   // read by lane l from lane l-1; lane 0 wraps to 31
            if (lane == 31) {
                if (wv == 0) sm = (j == 0) ? eprev : c[j - 1];
                else         sm = (j == 0) ? c[G - 1] : c2[j - 1];
            }
            float4 sn = cur;   // read by lane l from lane l+1; lane 31 wraps to 0
            if (lane == 0) {
                if (wv == 0) sn = (j == G - 1) ? c2[0] : c[j + 1];
                else         sn = (j == G - 1) ? enext : c2[j + 1];
            }

            float4 m, n;
            m.x = __shfl_sync(FULL, sm.x, up);
            m.y = __shfl_sync(FULL, sm.y, up);
            m.z = __shfl_sync(FULL, sm.z, up);
            m.w = __shfl_sync(FULL, sm.w, up);
            n.x = __shfl_sync(FULL, sn.x, dn);
            n.y = __shfl_sync(FULL, sn.y, dn);
            n.z = __shfl_sync(FULL, sn.z, dn);
            n.w = __shfl_sync(FULL, sn.w, dn);

            float a0 = m.x,   a1 = m.y,   a2  = m.z,   a3  = m.w;
            float a4 = cur.x, a5 = cur.y, a6  = cur.z, a7  = cur.w;
            float a8 = n.x,   a9 = n.y,   a10 = n.z,   a11 = n.w;

            float4 o;
            o.x = a0*k0 + a1*k1 + a2*k2 + a3*k3 + a4*k4 + a5*k5 + a6*k6 + a7*k7 + a8*k8;
            o.y = a1*k0 + a2*k1 + a3*k2 + a4*k3 + a5*k4 + a6*k5 + a7*k6 + a8*k7 + a9*k8;
            o.z = a2*k0 + a3*k1 + a4*k2 + a5*k3 + a6*k4 + a7*k5 + a8*k6 + a9*k7 + a10*k8;
            o.w = a3*k0 + a4*k1 + a5*k2 + a6*k3 + a7*k4 + a8*k5 + a9*k6 + a10*k7 + a11*k8;

            __stcs(reinterpret_cast<float4*>(
                orow + ((qw + (wv * G + j) * 32 + lane) << 2)), o);
        }
    }
}

extern "C" void kernel_launch(void* const* d_in, const int* in_sizes, int n_in,
                              void* d_out, int out_size)
{
    const float* x = (const float*)d_in[0];
    const float* w = (const float*)d_in[1];
    float* out = (float*)d_out;

    // total quads = 16,777,216 ; 2048 quads per block -> 8192 blocks
    dim3 grid((Bc * Fc * QUADS_PER_ROW) / (256 * QPT));
    dwconv1d_kernel<<<grid, 256>>>(x, w, out);
}

// round 13
// speedup vs baseline: 1.1216x; 1.1216x over previous
#include <cuda_runtime.h>

// Depthwise 1D conv: B=8, F=64, L=131072, K=9, pad=4 (SAME).
// x:      (B, F, L) float32, row (b,f) at (b*F + f)*L
// kernel: (F, 1, 9) float32
// out:    (F, B, 1, L) float32, row (f,b) at (f*B + b)*L
//
// Best-known structure (R10): 4 warp-strided quads per thread, all LDG/STG
// lane-adjacent (fully coalesced). Halo entirely via lane-wrap indexed
// shuffles; cross-chunk halo register-resident (lane31 carries c[j-1],
// lane0 carries c[j+1]). Only 2 true edge loads per warp, issued AFTER the
// main loads so the critical-path loads sit first in the L1tex FIFO.
// __ldcs/__stcs: both streams touched once -> evict-first, no L2 thrash.

#define Lc 131072
#define Fc 64
#define Bc 8
#define QUADS_PER_ROW (Lc / 4)            // 32768 = 2^15
#define QPT 4                             // quads per thread

__global__ __launch_bounds__(256) void dwconv1d_kernel(
    const float* __restrict__ x,
    const float* __restrict__ w,
    float* __restrict__ out)
{
    const unsigned FULL = 0xFFFFFFFFu;
    int lane = threadIdx.x & 31;
    int warp = threadIdx.x >> 5;

    // Block covers 1024 contiguous quads, all within one row (32768 % 1024 == 0)
    int qblock = blockIdx.x * (256 * QPT);
    int row = qblock >> 15;               // b*F + f
    int f = row & (Fc - 1);
    int b = row >> 6;

    const float* xr = x + (size_t)row * Lc;
    float* orow = out + ((size_t)(f * Bc + b)) * Lc;

    // 9 warp-uniform weight loads (whole block shares f)
    const float* wf = w + f * 9;
    float k0 = wf[0], k1 = wf[1], k2 = wf[2], k3 = wf[3], k4 = wf[4],
          k5 = wf[5], k6 = wf[6], k7 = wf[7], k8 = wf[8];

    // Warp's within-row quad base (warp spans quads [qw, qw+128))
    int qw = (qblock & (QUADS_PER_ROW - 1)) + warp * (32 * QPT);

    // ---- Main loads first: critical path heads the L1tex FIFO ----
    float4 c[QPT];
#pragma unroll
    for (int j = 0; j < QPT; j++)
        c[j] = __ldcs(reinterpret_cast<const float4*>(xr + ((qw + j * 32 + lane) << 2)));

    // Edge quads: only the wrap lane's value is ever read through the shuffle.
    float4 eprev = make_float4(0.f, 0.f, 0.f, 0.f);  // quad qw-1   (lane 31)
    float4 enext = make_float4(0.f, 0.f, 0.f, 0.f);  // quad qw+128 (lane 0)
    if (lane == 31 && qw != 0)
        eprev = __ldcs(reinterpret_cast<const float4*>(xr + (qw << 2) - 4));
    if (lane == 0 && qw + 32 * QPT != QUADS_PER_ROW)
        enext = __ldcs(reinterpret_cast<const float4*>(xr + ((qw + 32 * QPT) << 2)));

    // ---- Per-quad halo via indexed shuffle + FMA tree + store ----
    int up = (lane + 31) & 31;   // lane-1 mod 32
    int dn = (lane + 1) & 31;    // lane+1 mod 32
#pragma unroll
    for (int j = 0; j < QPT; j++) {
        // Source regs: wrap lanes carry the adjacent chunk's quad.
        float4 sm = c[j];        // lane l reads lane l-1; lane 0 reads lane 31
        if (lane == 31) sm = (j == 0) ? eprev : c[j - 1];
        float4 sn = c[j];        // lane l reads lane l+1; lane 31 reads lane 0
        if (lane == 0)  sn = (j == QPT - 1) ? enext : c[j + 1];

        float4 m, n;
        m.x = __shfl_sync(FULL, sm.x, up);
        m.y = __shfl_sync(FULL, sm.y, up);
        m.z = __shfl_sync(FULL, sm.z, up);
        m.w = __shfl_sync(FULL, sm.w, up);
        n.x = __shfl_sync(FULL, sn.x, dn);
        n.y = __shfl_sync(FULL, sn.y, dn);
        n.z = __shfl_sync(FULL, sn.z, dn);
        n.w = __shfl_sync(FULL, sn.w, dn);

        float a0 = m.x,    a1 = m.y,    a2  = m.z,    a3  = m.w;
        float a4 = c[j].x, a5 = c[j].y, a6  = c[j].z, a7  = c[j].w;
        float a8 = n.x,    a9 = n.y,    a10 = n.z,    a11 = n.w;

        float4 o;
        o.x = a0*k0 + a1*k1 + a2*k2 + a3*k3 + a4*k4 + a5*k5 + a6*k6 + a7*k7 + a8*k8;
        o.y = a1*k0 + a2*k1 + a3*k2 + a4*k3 + a5*k4 + a6*k5 + a7*k6 + a8*k7 + a9*k8;
        o.z = a2*k0 + a3*k1 + a4*k2 + a5*k3 + a6*k4 + a7*k5 + a8*k6 + a9*k7 + a10*k8;
        o.w = a3*k0 + a4*k1 + a5*k2 + a6*k3 + a7*k4 + a8*k5 + a9*k6 + a10*k7 + a11*k8;

        __stcs(reinterpret_cast<float4*>(orow + ((qw + j * 32 + lane) << 2)), o);
    }
}

extern "C" void kernel_launch(void* const* d_in, const int* in_sizes, int n_in,
                              void* d_out, int out_size)
{
    const float* x = (const float*)d_in[0];
    const float* w = (const float*)d_in[1];
    float* out = (float*)d_out;

    // total quads = 16,777,216 ; 1024 quads per block -> 16384 blocks
    dim3 grid((Bc * Fc * QUADS_PER_ROW) / (256 * QPT));
    dwconv1d_kernel<<<grid, 256>>>(x, w, out);
}